// round 16
// baseline (speedup 1.0000x reference)
#include <cuda_runtime.h>
#include <cuda_fp16.h>
#include <math.h>
#include <stdint.h>

#define NRES 8192
#define NK   48
#define NH   128

__device__ float g_Pi[NRES * NH];
__device__ float g_Pj[NRES * NH];
__device__ float g_Ps[NRES * NH];
__device__ float g_S [NRES * NH];
__device__ __half g_fW1h[512 * 128];    // fW1^T fp16: [n=512][k=128]
__device__ __half g_fW2h[128 * 512];    // fW2^T fp16: [n=128][k=512]
__device__ __half g_mWh[3 * 128 * 128]; // mW1 parts a/b/d as [n][k] fp16
__device__ __half g_nh16[NRES * NH];    // node_h fp16
__device__ __half g_se16[NRES * NH];    // seq_emb fp16

// exact-form gelu via A&S 7.1.26 erf (abs err ~1.5e-7)
__device__ __forceinline__ float gelu_fast(float x) {
    float u  = 0.7071067811865475f * x;
    float au = fabsf(u);
    float t  = __fdividef(1.0f, fmaf(0.3275911f, au, 1.0f));
    float p  = t * fmaf(t, fmaf(t, fmaf(t, fmaf(t, 1.061405429f, -1.453152027f),
                                        1.421413741f), -0.284496736f), 0.254829592f);
    float e  = __expf(-au * au);
    float er = copysignf(fmaf(-p, e, 1.0f), u);
    return 0.5f * x * (1.0f + er);
}
__device__ __forceinline__ uint32_t smem_u32(const void* p) {
    uint32_t a;
    asm("{ .reg .u64 t; cvta.to.shared.u64 t, %1; cvt.u32.u64 %0, t; }" : "=r"(a) : "l"(p));
    return a;
}
__device__ __forceinline__ uint32_t pack_h2(float a, float b) {
    __half2 h = __floats2half2_rn(a, b);
    return *reinterpret_cast<uint32_t*>(&h);
}
__device__ __forceinline__ void ldm_x4(uint32_t& r0, uint32_t& r1, uint32_t& r2, uint32_t& r3, uint32_t a) {
    asm volatile("ldmatrix.sync.aligned.m8n8.x4.shared.b16 {%0,%1,%2,%3}, [%4];"
                 : "=r"(r0), "=r"(r1), "=r"(r2), "=r"(r3) : "r"(a));
}
__device__ __forceinline__ void ldm_x2(uint32_t& r0, uint32_t& r1, uint32_t a) {
    asm volatile("ldmatrix.sync.aligned.m8n8.x2.shared.b16 {%0,%1}, [%2];"
                 : "=r"(r0), "=r"(r1) : "r"(a));
}
__device__ __forceinline__ void mma_f16(float* c, uint32_t a0, uint32_t a1, uint32_t a2, uint32_t a3,
                                        uint32_t b0, uint32_t b1) {
    asm volatile("mma.sync.aligned.m16n8k16.row.col.f32.f16.f16.f32 "
                 "{%0,%1,%2,%3}, {%4,%5,%6,%7}, {%8,%9}, {%0,%1,%2,%3};"
                 : "+f"(c[0]), "+f"(c[1]), "+f"(c[2]), "+f"(c[3])
                 : "r"(a0), "r"(a1), "r"(a2), "r"(a3), "r"(b0), "r"(b1));
}

// ---------------------------------------------------------------------------
// Kernel 0: all fp16 operand conversions (once, ~5us)
// ---------------------------------------------------------------------------
__global__ __launch_bounds__(256) void k0_conv(const float* __restrict__ node_h,
                                               const float* __restrict__ seq_emb,
                                               const float* __restrict__ mW1,
                                               const float* __restrict__ fW1,
                                               const float* __restrict__ fW2) {
    const int gt = blockIdx.x * 256 + threadIdx.x;   // 65536 threads
    for (int i = gt; i < NRES * NH; i += 65536) {
        g_nh16[i] = __float2half_rn(node_h[i]);
        g_se16[i] = __float2half_rn(seq_emb[i]);
    }
    if (gt < 49152) {
        const int which = gt >> 14, r = gt & 16383;
        const int n = r >> 7, k = r & 127;
        const int kb = (which == 0) ? 0 : (which == 1 ? 128 : 384);
        g_mWh[gt] = __float2half_rn(mW1[(size_t)(kb + k) * NH + n]);
    }
    {
        const int n = gt >> 7, k = gt & 127;
        g_fW1h[gt] = __float2half_rn(fW1[(size_t)k * 512 + n]);
    }
    {
        const int n = gt >> 9, k = gt & 511;
        g_fW2h[gt] = __float2half_rn(fW2[(size_t)k * 128 + n]);
    }
}

// ---------------------------------------------------------------------------
// Kernel 1: Pi/Pj/Ps via fp16 HMMA (proven round-15 config)
// ---------------------------------------------------------------------------
#define LDB 272u
#define K1_A 0u
#define K1_W 17408u
#define K1_TOT 52224u

__global__ __launch_bounds__(256) void k1_hmma() {
    extern __shared__ char smc[];
    const uint32_t sb = smem_u32(smc);
    const int tid = threadIdx.x;
    const int w   = tid >> 5, lane = tid & 31;
    const int gid = lane >> 2, t4 = lane & 3;
    const int wm  = w >> 2, wn = w & 3;
    const int m_base = wm * 32, n_base = wn * 32;
    const int m0    = blockIdx.x * 64;
    const int which = blockIdx.y;

    const __half* Asrc = ((which == 2) ? g_se16 : g_nh16) + (size_t)m0 * NH;
    const __half* Wsrc = g_mWh + which * 16384;
    float* out = (which == 0) ? g_Pi : (which == 1 ? g_Pj : g_Ps);

    for (int i = tid; i < 1024; i += 256) {
        const int r = i >> 4, c = i & 15;
        asm volatile("cp.async.cg.shared.global [%0], [%1], 16;"
                     :: "r"(sb + K1_A + (uint32_t)r * LDB + (uint32_t)c * 16u),
                        "l"((const char*)Asrc + (size_t)r * 256 + (size_t)c * 16));
    }
    for (int i = tid; i < 2048; i += 256) {
        const int r = i >> 4, c = i & 15;
        asm volatile("cp.async.cg.shared.global [%0], [%1], 16;"
                     :: "r"(sb + K1_W + (uint32_t)r * LDB + (uint32_t)c * 16u),
                        "l"((const char*)Wsrc + (size_t)r * 256 + (size_t)c * 16));
    }
    asm volatile("cp.async.commit_group;" ::: "memory");
    asm volatile("cp.async.wait_group 0;" ::: "memory");
    __syncthreads();

    const uint32_t aBase = sb + K1_A + (uint32_t)(m_base + (lane & 15)) * LDB
                         + (uint32_t)((lane >> 4) * 16);
    const uint32_t b_off = (uint32_t)(lane & 7) * LDB + (uint32_t)(((lane >> 3) & 1) * 16);
    uint32_t bOf[4];
#pragma unroll
    for (int j = 0; j < 4; j++)
        bOf[j] = sb + K1_W + (uint32_t)(n_base + j * 8) * LDB + b_off;

    float acc[2][4][4];
#pragma unroll
    for (int i = 0; i < 2; i++)
#pragma unroll
        for (int j = 0; j < 4; j++)
#pragma unroll
            for (int q = 0; q < 4; q++) acc[i][j][q] = 0.f;

#pragma unroll
    for (int ks = 0; ks < 8; ks++) {
        const uint32_t ko = (uint32_t)ks * 32u;
        uint32_t a[2][4], bh[4][2];
        ldm_x4(a[0][0], a[0][1], a[0][2], a[0][3], aBase + ko);
        ldm_x4(a[1][0], a[1][1], a[1][2], a[1][3], aBase + 16u * LDB + ko);
#pragma unroll
        for (int j = 0; j < 4; j++)
            ldm_x2(bh[j][0], bh[j][1], bOf[j] + ko);
#pragma unroll
        for (int i = 0; i < 2; i++)
#pragma unroll
            for (int j = 0; j < 4; j++)
                mma_f16(acc[i][j], a[i][0], a[i][1], a[i][2], a[i][3], bh[j][0], bh[j][1]);
    }

#pragma unroll
    for (int i = 0; i < 2; i++) {
        const int rA = m_base + i * 16 + gid;
#pragma unroll
        for (int j = 0; j < 4; j++) {
            const int n_e = n_base + j * 8 + t4 * 2;
            *(float2*)&out[(size_t)(m0 + rA) * NH + n_e]     = make_float2(acc[i][j][0], acc[i][j][1]);
            *(float2*)&out[(size_t)(m0 + rA + 8) * NH + n_e] = make_float2(acc[i][j][2], acc[i][j][3]);
        }
    }
}

// ---------------------------------------------------------------------------
// Kernel 2: per-edge MLP, single-pass fp16 HMMA. NEW: no fp32 staging buffer
// (direct LDG E build); smem 111.6KB -> 2 CTAs/SM; M=128 tile preserved.
// Cross-CTA overlap hides build/epilogue phases.
// ---------------------------------------------------------------------------
#define S_W1  0u
#define S_W2  34816u
#define S_A   69632u
#define S_SSUM 104448u   // 8*128 fp32
#define S_IDX 108544u    // [2][128] int
#define S_AM  109568u    // [2][128] float
#define S_MB  110592u    // 256 fp32
#define S_K2TOT 111616u

__device__ __forceinline__ void idx_prefetch(uint32_t sb, const int* edge_idx,
                                             const float* ar_mask, int row0, int pp, int tid) {
    if (tid < 128)
        asm volatile("cp.async.ca.shared.global [%0], [%1], 4;"
                     :: "r"(sb + S_IDX + (uint32_t)pp * 512u + (uint32_t)tid * 4u),
                        "l"(edge_idx + row0 + tid));
    else if (tid < 256)
        asm volatile("cp.async.ca.shared.global [%0], [%1], 4;"
                     :: "r"(sb + S_AM + (uint32_t)pp * 512u + (uint32_t)(tid - 128) * 4u),
                        "l"(ar_mask + row0 + (tid - 128)));
    asm volatile("cp.async.commit_group;" ::: "memory");
}

__global__ __launch_bounds__(512, 2) void k2_msg(const float* __restrict__ edge_h,
                                                 const int*   __restrict__ edge_idx,
                                                 const float* __restrict__ ar_mask,
                                                 const float* __restrict__ mW1,
                                                 const float* __restrict__ mb1,
                                                 const float* __restrict__ mW2,
                                                 const float* __restrict__ mb2,
                                                 int ngroups) {
    extern __shared__ char sm[];
    const int tid  = threadIdx.x;
    const int w    = tid >> 5, lane = tid & 31;
    const int gid  = lane >> 2, t4 = lane & 3;
    const int wm   = w >> 2, wn = w & 3;
    const int m_base = wm * 32, n_base = wn * 32;
    const uint32_t sb = smem_u32(sm);

    float* SSUM = (float*)(sm + S_SSUM);
    float* MB   = (float*)(sm + S_MB);

    if (tid < 128) MB[tid] = mb1[tid];
    else if (tid < 256) MB[tid] = mb2[tid - 128];

    // stage W1c^T / W2^T as fp16 (coalesced reads)
    for (int idx = tid; idx < 16384; idx += 512) {
        const int n = idx & 127, k = idx >> 7;
        float w1 = mW1[(size_t)(256 + k) * NH + n];
        float w2 = mW2[(size_t)k * NH + n];
        const uint32_t o = (uint32_t)n * LDB + (uint32_t)k * 2u;
        *(__half*)(sm + S_W1 + o) = __float2half_rn(w1);
        *(__half*)(sm + S_W2 + o) = __float2half_rn(w2);
    }

    const uint32_t aBase = sb + S_A + (uint32_t)(m_base + (lane & 15)) * LDB
                         + (uint32_t)((lane >> 4) * 16);
    const uint32_t b_off = (uint32_t)(lane & 7) * LDB + (uint32_t)(((lane >> 3) & 1) * 16);
    uint32_t bOf[4];
#pragma unroll
    for (int j = 0; j < 4; j++)
        bOf[j] = (uint32_t)(n_base + j * 8) * LDB + b_off;

    int pp = 0;
    if ((int)blockIdx.x < ngroups)
        idx_prefetch(sb, edge_idx, ar_mask, blockIdx.x * 384, 0, tid);

    for (int g = blockIdx.x; g < ngroups; g += gridDim.x) {
        for (int t = 0; t < 3; t++) {
            const int row0 = g * 384 + t * 128;
            asm volatile("cp.async.wait_group 0;" ::: "memory");
            __syncthreads();            // idx/am visible; prev GEMM2 reads of A done
            if (t == 0)
                for (int i = tid; i < 1024; i += 512) SSUM[i] = 0.f;

            // build A: direct LDG of 128 rows x 128 cols fp32 -> fp16
#pragma unroll
            for (int k2i = 0; k2i < 8; k2i++) {
                const int i = tid + k2i * 512;
                const int r = i >> 5, c4 = i & 31;
                float4 e = ((const float4*)(edge_h + (size_t)(row0 + r) * NH))[c4];
                const uint32_t o = (uint32_t)r * LDB + (uint32_t)c4 * 8u;
                *(uint2*)(sm + S_A + o) = make_uint2(pack_h2(e.x, e.y), pack_h2(e.z, e.w));
            }
            __syncthreads();

            // prefetch next tile's idx/am
            {
                int nt = t + 1, ng = g;
                if (nt == 3) { nt = 0; ng = g + gridDim.x; }
                if (ng < ngroups)
                    idx_prefetch(sb, edge_idx, ar_mask, ng * 384 + nt * 128, pp ^ 1, tid);
            }

            const int*   IDXc = (const int*)(sm + S_IDX) + pp * 128;
            const float* AMc  = (const float*)(sm + S_AM) + pp * 128;

            float acc[2][4][4];

            // GEMM1 acc init: Pi + Pj + am*Ps + mb1
#pragma unroll
            for (int i = 0; i < 2; i++) {
                const int rA = m_base + i * 16 + gid;
                const int resA = (row0 + rA) / NK,  resB = (row0 + rA + 8) / NK;
                const int nbrA = IDXc[rA],          nbrB = IDXc[rA + 8];
                const float amA = AMc[rA],          amB = AMc[rA + 8];
                const float* PiA = g_Pi + (size_t)resA * NH;
                const float* PiB = g_Pi + (size_t)resB * NH;
                const float* PjA = g_Pj + (size_t)nbrA * NH;
                const float* PjB = g_Pj + (size_t)nbrB * NH;
                const float* PsA = g_Ps + (size_t)nbrA * NH;
                const float* PsB = g_Ps + (size_t)nbrB * NH;
#pragma unroll
                for (int j = 0; j < 4; j++) {
                    const int n_e = n_base + j * 8 + t4 * 2;
                    float2 piA = *(const float2*)&PiA[n_e], piB = *(const float2*)&PiB[n_e];
                    float2 pjA = *(const float2*)&PjA[n_e], pjB = *(const float2*)&PjB[n_e];
                    float2 psA = *(const float2*)&PsA[n_e], psB = *(const float2*)&PsB[n_e];
                    float2 mb = *(const float2*)&MB[n_e];
                    acc[i][j][0] = piA.x + pjA.x + amA * psA.x + mb.x;
                    acc[i][j][1] = piA.y + pjA.y + amA * psA.y + mb.y;
                    acc[i][j][2] = piB.x + pjB.x + amB * psB.x + mb.x;
                    acc[i][j][3] = piB.y + pjB.y + amB * psB.y + mb.y;
                }
            }
            // GEMM1: acc += E @ W1
#pragma unroll
            for (int ks = 0; ks < 8; ks++) {
                const uint32_t ko = (uint32_t)ks * 32u;
                uint32_t a[2][4], bh[4][2];
                ldm_x4(a[0][0], a[0][1], a[0][2], a[0][3], aBase + ko);
                ldm_x4(a[1][0], a[1][1], a[1][2], a[1][3], aBase + 16u * LDB + ko);
#pragma unroll
                for (int j = 0; j < 4; j++)
                    ldm_x2(bh[j][0], bh[j][1], sb + S_W1 + bOf[j] + ko);
#pragma unroll
                for (int i = 0; i < 2; i++)
#pragma unroll
                    for (int j = 0; j < 4; j++)
                        mma_f16(acc[i][j], a[i][0], a[i][1], a[i][2], a[i][3], bh[j][0], bh[j][1]);
            }
            __syncthreads();

            // epilogue 1: X1 = gelu(acc) -> A
#pragma unroll
            for (int i = 0; i < 2; i++) {
                const int m_e = m_base + i * 16 + gid;
#pragma unroll
                for (int j = 0; j < 4; j++) {
                    const int n_e = n_base + j * 8 + t4 * 2;
                    float v0 = gelu_fast(acc[i][j][0]), v1 = gelu_fast(acc[i][j][1]);
                    float v2 = gelu_fast(acc[i][j][2]), v3 = gelu_fast(acc[i][j][3]);
                    const uint32_t o0 = (uint32_t)m_e * LDB + (uint32_t)n_e * 2u;
                    const uint32_t o1 = o0 + 8u * LDB;
                    *(uint32_t*)(sm + S_A + o0) = pack_h2(v0, v1);
                    *(uint32_t*)(sm + S_A + o1) = pack_h2(v2, v3);
                }
            }
            __syncthreads();

            // GEMM2: acc = mb2 + X1 @ W2
#pragma unroll
            for (int i = 0; i < 2; i++)
#pragma unroll
                for (int j = 0; j < 4; j++) {
                    float2 mb = *(const float2*)&MB[128 + n_base + j * 8 + t4 * 2];
                    acc[i][j][0] = mb.x; acc[i][j][1] = mb.y;
                    acc[i][j][2] = mb.x; acc[i][j][3] = mb.y;
                }
#pragma unroll
            for (int ks = 0; ks < 8; ks++) {
                const uint32_t ko = (uint32_t)ks * 32u;
                uint32_t a[2][4], bh[4][2];
                ldm_x4(a[0][0], a[0][1], a[0][2], a[0][3], aBase + ko);
                ldm_x4(a[1][0], a[1][1], a[1][2], a[1][3], aBase + 16u * LDB + ko);
#pragma unroll
                for (int j = 0; j < 4; j++)
                    ldm_x2(bh[j][0], bh[j][1], sb + S_W2 + bOf[j] + ko);
#pragma unroll
                for (int i = 0; i < 2; i++)
#pragma unroll
                    for (int j = 0; j < 4; j++)
                        mma_f16(acc[i][j], a[i][0], a[i][1], a[i][2], a[i][3], bh[j][0], bh[j][1]);
            }

            // epilogue 2: gelu -> warp-shuffle segmented reduce -> few atomics
            {
                const int R0  = t * 128 + m_base;
                const int rl0 = R0 / NK;
                const int bb  = (rl0 + 1) * NK - R0;
#pragma unroll
                for (int j = 0; j < 4; j++) {
#pragma unroll
                    for (int p = 0; p < 2; p++) {
                        float y0 = gelu_fast(acc[0][j][p]);
                        float y1 = gelu_fast(acc[0][j][p + 2]);
                        float y2 = gelu_fast(acc[1][j][p]);
                        float y3 = gelu_fast(acc[1][j][p + 2]);
                        float s0 = 0.f, s1 = 0.f;
                        if (gid      < bb) s0 += y0; else s1 += y0;
                        if (gid + 8  < bb) s0 += y1; else s1 += y1;
                        if (gid + 16 < bb) s0 += y2; else s1 += y2;
                        if (gid + 24 < bb) s0 += y3; else s1 += y3;
#pragma unroll
                        for (int o = 4; o <= 16; o <<= 1) {
                            s0 += __shfl_xor_sync(0xffffffffu, s0, o);
                            s1 += __shfl_xor_sync(0xffffffffu, s1, o);
                        }
                        if (gid == 0) {
                            const int c = n_base + j * 8 + t4 * 2 + p;
                            atomicAdd(&SSUM[rl0 * 128 + c], s0);
                            if (bb < 32) atomicAdd(&SSUM[(rl0 + 1) * 128 + c], s1);
                        }
                    }
                }
            }
            pp ^= 1;
        }
        __syncthreads();
        for (int i = tid; i < 1024; i += 512)
            g_S[(size_t)g * 1024 + i] = SSUM[i];
    }
}

// ---------------------------------------------------------------------------
// Kernel 3: GEMM3+LN1 fp32 (mW3 2x32KB chunks); FFN fp16 HMMA, streamed
// pre-converted weights; 93.7KB smem, 2 CTAs/SM (proven round-14/15)
// ---------------------------------------------------------------------------
#define K3_H1  0u
#define K3_A16 16896u
#define K3_T16 25600u
#define K3_WB  58880u
#define K3_TOT 93696u
#define LDT 1040u

__device__ __forceinline__ void k3_wload(uint32_t dst, const __half* src,
                                         uint32_t row_stride_b, int tid) {
#pragma unroll
    for (int i = 0; i < 8; i++) {
        const int c = tid + i * 256;
        const int r = c >> 4, col = c & 15;
        asm volatile("cp.async.cg.shared.global [%0], [%1], 16;"
                     :: "r"(dst + (uint32_t)r * LDB + (uint32_t)col * 16u),
                        "l"((const char*)src + (size_t)r * row_stride_b + (size_t)col * 16));
    }
    asm volatile("cp.async.commit_group;" ::: "memory");
}

__global__ __launch_bounds__(256, 2) void k3_ff(const float* __restrict__ node_h,
                                                const float* __restrict__ mW3,
                                                const float* __restrict__ mb3,
                                                const float* __restrict__ fb1,
                                                const float* __restrict__ fb2,
                                                const float* __restrict__ g1,
                                                const float* __restrict__ b1,
                                                const float* __restrict__ g2,
                                                const float* __restrict__ b2,
                                                float* __restrict__ out) {
    extern __shared__ char smc[];
    float* H1sh = (float*)(smc + K3_H1);
    float* Ssh  = (float*)(smc + K3_T16);
    float* WfA  = (float*)(smc + K3_WB);
    const uint32_t sb = smem_u32(smc);

    const int tid = threadIdx.x;
    const int w   = tid >> 5, lane = tid & 31;
    const int gid = lane >> 2, t4 = lane & 3;
    const int wm  = w >> 2, wn = w & 3;
    const int m0  = blockIdx.x * 32;
    const int tc  = tid & 15, tr = tid >> 4;

    for (int i = tid; i < 1024; i += 256) {
        int r = i >> 5, c4 = i & 31;
        *(float4*)&Ssh[r * 132 + c4 * 4] = ((const float4*)(g_S + (size_t)(m0 + r) * NH))[c4];
    }
    {
        float acc[2][8];
#pragma unroll
        for (int i = 0; i < 2; i++)
#pragma unroll
            for (int j = 0; j < 8; j++)
                acc[i][j] = 48.f * mb3[(j < 4 ? tc * 4 + j : 64 + tc * 4 + j - 4)];
        for (int h = 0; h < 2; h++) {
            __syncthreads();
            for (int i = tid; i < 2048; i += 256) {
                int k = i >> 5, c4 = i & 31;
                ((float4*)&WfA[k * 128])[c4] = ((const float4*)&mW3[(size_t)(h * 64 + k) * 128])[c4];
            }
            __syncthreads();
#pragma unroll 4
            for (int kk = 0; kk < 64; kk++) {
                float4 b0 = *(const float4*)&WfA[kk * 128 + tc * 4];
                float4 b1v = *(const float4*)&WfA[kk * 128 + 64 + tc * 4];
#pragma unroll
                for (int i = 0; i < 2; i++) {
                    float a = Ssh[(tr * 2 + i) * 132 + h * 64 + kk];
                    acc[i][0] = fmaf(a, b0.x, acc[i][0]); acc[i][1] = fmaf(a, b0.y, acc[i][1]);
                    acc[i][2] = fmaf(a, b0.z, acc[i][2]); acc[i][3] = fmaf(a, b0.w, acc[i][3]);
                    acc[i][4] = fmaf(a, b1v.x, acc[i][4]); acc[i][5] = fmaf(a, b1v.y, acc[i][5]);
                    acc[i][6] = fmaf(a, b1v.z, acc[i][6]); acc[i][7] = fmaf(a, b1v.w, acc[i][7]);
                }
            }
        }
#pragma unroll
        for (int i = 0; i < 2; i++) {
            const float* nrow = node_h + (size_t)(m0 + tr * 2 + i) * NH;
            float4 n0 = *(const float4*)&nrow[tc * 4];
            float4 n1 = *(const float4*)&nrow[64 + tc * 4];
            float* hrow = &H1sh[(tr * 2 + i) * 132];
            hrow[tc * 4 + 0] = acc[i][0] + n0.x; hrow[tc * 4 + 1] = acc[i][1] + n0.y;
            hrow[tc * 4 + 2] = acc[i][2] + n0.z; hrow[tc * 4 + 3] = acc[i][3] + n0.w;
            hrow[64 + tc * 4 + 0] = acc[i][4] + n1.x; hrow[64 + tc * 4 + 1] = acc[i][5] + n1.y;
            hrow[64 + tc * 4 + 2] = acc[i][6] + n1.z; hrow[64 + tc * 4 + 3] = acc[i][7] + n1.w;
        }
    }
    __syncthreads();

    k3_wload(sb + K3_WB, g_fW1h, 256u, tid);

    for (int r = w; r < 32; r += 8) {
        const int c0 = lane * 4;
        float v0 = H1sh[r * 132 + c0], v1 = H1sh[r * 132 + c0 + 1];
        float v2 = H1sh[r * 132 + c0 + 2], v3 = H1sh[r * 132 + c0 + 3];
        float s = v0 + v1 + v2 + v3;
#pragma unroll
        for (int o = 16; o; o >>= 1) s += __shfl_xor_sync(0xffffffffu, s, o);
        float mu = s * (1.f / 128.f);
        float d0 = v0 - mu, d1 = v1 - mu, d2 = v2 - mu, d3 = v3 - mu;
        float q = d0 * d0 + d1 * d1 + d2 * d2 + d3 * d3;
#pragma unroll
        for (int o = 16; o; o >>= 1) q += __shfl_xor_sync(0xffffffffu, q, o);
        float rs = rsqrtf(q * (1.f / 128.f) + 1e-5f);
        H1sh[r * 132 + c0]     = d0 * rs * g1[c0]     + b1[c0];
        H1sh[r * 132 + c0 + 1] = d1 * rs * g1[c0 + 1] + b1[c0 + 1];
        H1sh[r * 132 + c0 + 2] = d2 * rs * g1[c0 + 2] + b1[c0 + 2];
        H1sh[r * 132 + c0 + 3] = d3 * rs * g1[c0 + 3] + b1[c0 + 3];
    }
    __syncthreads();

    {
        const int r = tid >> 3, c0 = (tid & 7) * 16;
        const float* hrow = &H1sh[r * 132 + c0];
        uint32_t pk[8];
#pragma unroll
        for (int j = 0; j < 8; j++) pk[j] = pack_h2(hrow[j * 2], hrow[j * 2 + 1]);
        char* dst = smc + K3_A16 + (uint32_t)r * LDB + (uint32_t)c0 * 2u;
        *(uint4*)dst        = make_uint4(pk[0], pk[1], pk[2], pk[3]);
        *(uint4*)(dst + 16) = make_uint4(pk[4], pk[5], pk[6], pk[7]);
    }

    const uint32_t aAddr1 = sb + K3_A16 + (uint32_t)(wm * 16 + (lane & 15)) * LDB
                          + (uint32_t)((lane >> 4) * 16);
    const uint32_t aAddr2 = sb + K3_T16 + (uint32_t)(wm * 16 + (lane & 15)) * LDT
                          + (uint32_t)((lane >> 4) * 16);
    const uint32_t b_off = (uint32_t)(lane & 7) * LDB + (uint32_t)(((lane >> 3) & 1) * 16);
    uint32_t bOf[4];
#pragma unroll
    for (int j = 0; j < 4; j++)
        bOf[j] = (uint32_t)(wn * 32 + j * 8) * LDB + b_off;
    const uint32_t WBa = sb + K3_WB;

    float acc2[4][4];
#pragma unroll
    for (int j = 0; j < 4; j++) {
        float2 fb = *(const float2*)&fb2[wn * 32 + j * 8 + t4 * 2];
        acc2[j][0] = fb.x; acc2[j][1] = fb.y; acc2[j][2] = fb.x; acc2[j][3] = fb.y;
    }

    for (int nc = 0; nc < 4; nc++) {
        asm volatile("cp.async.wait_group 0;" ::: "memory");
        __syncthreads();
        float acc[4][4];
#pragma unroll
        for (int j = 0; j < 4; j++) {
            float2 fb = *(const float2*)&fb1[nc * 128 + wn * 32 + j * 8 + t4 * 2];
            acc[j][0] = fb.x; acc[j][1] = fb.y; acc[j][2] = fb.x; acc[j][3] = fb.y;
        }
#pragma unroll
        for (int ks = 0; ks < 8; ks++) {
            const uint32_t ko = (uint32_t)ks * 32u;
            uint32_t a[4], bh[4][2];
            ldm_x4(a[0], a[1], a[2], a[3], aAddr1 + ko);
#pragma unroll
            for (int j = 0; j < 4; j++)
                ldm_x2(bh[j][0], bh[j][1], WBa + bOf[j] + ko);
#pragma unroll
            for (int j = 0; j < 4; j++)
                mma_f16(acc[j], a[0], a[1], a[2], a[3], bh[j][0], bh[j][1]);
        }
        __syncthreads();
        if (nc < 3)      k3_wload(WBa, g_fW1h + (nc + 1) * 16384, 256u, tid);
        else             k3_wload(WBa, g_fW2h,                    1024u, tid);
#pragma unroll
        for (int j = 0; j < 4; j++) {
            const int r0 = wm * 16 + gid;
            const int cg = nc * 128 + wn * 32 + j * 8 + t4 * 2;
            *(uint32_t*)(smc + K3_T16 + (uint32_t)r0 * LDT + (uint32_t)cg * 2u) =
                pack_h2(gelu_fast(acc[j][0]), gelu_fast(acc[j][1]));
            *(uint32_t*)(smc + K3_T16 + (uint32_t)(r0 + 8) * LDT + (uint32_t)cg * 2u) =
                pack_h2(gelu_fast(acc[j][2]), gelu_fast(acc[j][3]));
        }
    }

    for (int kc = 0; kc < 4; kc++) {
        asm volatile("cp.async.wait_group 0;" ::: "memory");
        __syncthreads();
#pragma unroll
        for (int ks = 0; ks < 8; ks++) {
            const uint32_t ko = (uint32_t)ks * 32u;
            uint32_t a[4], bh[4][2];
            ldm_x4(a[0], a[1], a[2], a[3], aAddr2 + (uint32_t)kc * 256u + ko);
#pragma unroll
            for (int j = 0; j < 4; j++)
                ldm_x2(bh[j][0], bh[j][1], WBa + bOf[j] + ko);
#pragma unroll
            for (int j = 0; j < 4; j++)
                mma_f16(acc2[j], a[0], a[1], a[2], a[3], bh[j][0], bh[j][1]);
        }
        __syncthreads();
        if (kc < 3) k3_wload(WBa, g_fW2h + (kc + 1) * 128, 1024u, tid);
    }

    __syncthreads();
    float* Vsh = (float*)(smc + K3_T16);
#pragma unroll
    for (int j = 0; j < 4; j++) {
        const int r0 = wm * 16 + gid, r1 = r0 + 8;
        const int c = wn * 32 + j * 8 + t4 * 2;
        Vsh[r0 * 132 + c]     = H1sh[r0 * 132 + c]     + acc2[j][0];
        Vsh[r0 * 132 + c + 1] = H1sh[r0 * 132 + c + 1] + acc2[j][1];
        Vsh[r1 * 132 + c]     = H1sh[r1 * 132 + c]     + acc2[j][2];
        Vsh[r1 * 132 + c + 1] = H1sh[r1 * 132 + c + 1] + acc2[j][3];
    }
    __syncthreads();
    for (int r = w; r < 32; r += 8) {
        const int c0 = lane * 4;
        float v0 = Vsh[r * 132 + c0], v1 = Vsh[r * 132 + c0 + 1];
        float v2 = Vsh[r * 132 + c0 + 2], v3 = Vsh[r * 132 + c0 + 3];
        float s = v0 + v1 + v2 + v3;
#pragma unroll
        for (int o = 16; o; o >>= 1) s += __shfl_xor_sync(0xffffffffu, s, o);
        float mu = s * (1.f / 128.f);
        float d0 = v0 - mu, d1 = v1 - mu, d2 = v2 - mu, d3 = v3 - mu;
        float q = d0 * d0 + d1 * d1 + d2 * d2 + d3 * d3;
#pragma unroll
        for (int o = 16; o; o >>= 1) q += __shfl_xor_sync(0xffffffffu, q, o);
        float rs = rsqrtf(q * (1.f / 128.f) + 1e-5f);
        float4 o4;
        o4.x = d0 * rs * g2[c0]     + b2[c0];
        o4.y = d1 * rs * g2[c0 + 1] + b2[c0 + 1];
        o4.z = d2 * rs * g2[c0 + 2] + b2[c0 + 2];
        o4.w = d3 * rs * g2[c0 + 3] + b2[c0 + 3];
        *(float4*)&out[(size_t)(m0 + r) * NH + c0] = o4;
    }
}

// ---------------------------------------------------------------------------
extern "C" void kernel_launch(void* const* d_in, const int* in_sizes, int n_in,
                              void* d_out, int out_size) {
    const float* node_h   = (const float*)d_in[0];
    const float* edge_h   = (const float*)d_in[1];
    const int*   edge_idx = (const int*)d_in[2];
    const float* seq_emb  = (const float*)d_in[3];
    const float* ar_mask  = (const float*)d_in[4];
    const float* mW1 = (const float*)d_in[5];
    const float* mb1 = (const float*)d_in[6];
    const float* mW2 = (const float*)d_in[7];
    const float* mb2 = (const float*)d_in[8];
    const float* mW3 = (const float*)d_in[9];
    const float* mb3 = (const float*)d_in[10];
    const float* fW1 = (const float*)d_in[11];
    const float* fb1 = (const float*)d_in[12];
    const float* fW2 = (const float*)d_in[13];
    const float* fb2 = (const float*)d_in[14];
    const float* g1  = (const float*)d_in[15];
    const float* b1  = (const float*)d_in[16];
    const float* g2  = (const float*)d_in[17];
    const float* b2  = (const float*)d_in[18];
    float* out = (float*)d_out;

    int dev = 0;
    cudaGetDevice(&dev);
    int nsm = 148;
    cudaDeviceGetAttribute(&nsm, cudaDevAttrMultiProcessorCount, dev);

    cudaFuncSetAttribute(k1_hmma, cudaFuncAttributeMaxDynamicSharedMemorySize, (int)K1_TOT);
    cudaFuncSetAttribute(k2_msg,  cudaFuncAttributeMaxDynamicSharedMemorySize, (int)S_K2TOT);
    cudaFuncSetAttribute(k3_ff,   cudaFuncAttributeMaxDynamicSharedMemorySize, (int)K3_TOT);

    k0_conv<<<256, 256>>>(node_h, seq_emb, mW1, fW1, fW2);

    dim3 grid1(NRES / 64, 3);
    k1_hmma<<<grid1, 256, K1_TOT>>>();

    const int ngroups = NRES / 8;
    k2_msg<<<2 * nsm, 512, S_K2TOT>>>(edge_h, edge_idx, ar_mask,
                                      mW1, mb1, mW2, mb2, ngroups);

    k3_ff<<<NRES / 32, 256, K3_TOT>>>(node_h, mW3, mb3, fb1, fb2,
                                      g1, b1, g2, b2, out);
}

// round 17
// speedup vs baseline: 1.0860x; 1.0860x over previous
#include <cuda_runtime.h>
#include <cuda_fp16.h>
#include <math.h>
#include <stdint.h>

#define NRES 8192
#define NK   48
#define NH   128

__device__ float g_Pi[NRES * NH];
__device__ float g_Pj[NRES * NH];
__device__ float g_Ps[NRES * NH];
__device__ float g_S [NRES * NH];
__device__ __half g_fW1h[512 * 128];    // fW1^T fp16: [n=512][k=128]
__device__ __half g_fW2h[128 * 512];    // fW2^T fp16: [n=128][k=512]
__device__ __half g_mWh[3 * 128 * 128]; // mW1 parts a/b/d as [n][k] fp16
__device__ __half g_nh16[NRES * NH];    // node_h fp16
__device__ __half g_se16[NRES * NH];    // seq_emb fp16

// exact-form gelu via A&S 7.1.26 erf (abs err ~1.5e-7)
__device__ __forceinline__ float gelu_fast(float x) {
    float u  = 0.7071067811865475f * x;
    float au = fabsf(u);
    float t  = __fdividef(1.0f, fmaf(0.3275911f, au, 1.0f));
    float p  = t * fmaf(t, fmaf(t, fmaf(t, fmaf(t, 1.061405429f, -1.453152027f),
                                        1.421413741f), -0.284496736f), 0.254829592f);
    float e  = __expf(-au * au);
    float er = copysignf(fmaf(-p, e, 1.0f), u);
    return 0.5f * x * (1.0f + er);
}
__device__ __forceinline__ uint32_t smem_u32(const void* p) {
    uint32_t a;
    asm("{ .reg .u64 t; cvta.to.shared.u64 t, %1; cvt.u32.u64 %0, t; }" : "=r"(a) : "l"(p));
    return a;
}
__device__ __forceinline__ uint32_t pack_h2(float a, float b) {
    __half2 h = __floats2half2_rn(a, b);
    return *reinterpret_cast<uint32_t*>(&h);
}
__device__ __forceinline__ void ldm_x4(uint32_t& r0, uint32_t& r1, uint32_t& r2, uint32_t& r3, uint32_t a) {
    asm volatile("ldmatrix.sync.aligned.m8n8.x4.shared.b16 {%0,%1,%2,%3}, [%4];"
                 : "=r"(r0), "=r"(r1), "=r"(r2), "=r"(r3) : "r"(a));
}
__device__ __forceinline__ void ldm_x2(uint32_t& r0, uint32_t& r1, uint32_t a) {
    asm volatile("ldmatrix.sync.aligned.m8n8.x2.shared.b16 {%0,%1}, [%2];"
                 : "=r"(r0), "=r"(r1) : "r"(a));
}
__device__ __forceinline__ void mma_f16(float* c, uint32_t a0, uint32_t a1, uint32_t a2, uint32_t a3,
                                        uint32_t b0, uint32_t b1) {
    asm volatile("mma.sync.aligned.m16n8k16.row.col.f32.f16.f16.f32 "
                 "{%0,%1,%2,%3}, {%4,%5,%6,%7}, {%8,%9}, {%0,%1,%2,%3};"
                 : "+f"(c[0]), "+f"(c[1]), "+f"(c[2]), "+f"(c[3])
                 : "r"(a0), "r"(a1), "r"(a2), "r"(a3), "r"(b0), "r"(b1));
}

// ---------------------------------------------------------------------------
// Kernel 0: all fp16 operand conversions (once, ~5us)
// ---------------------------------------------------------------------------
__global__ __launch_bounds__(256) void k0_conv(const float* __restrict__ node_h,
                                               const float* __restrict__ seq_emb,
                                               const float* __restrict__ mW1,
                                               const float* __restrict__ fW1,
                                               const float* __restrict__ fW2) {
    const int gt = blockIdx.x * 256 + threadIdx.x;   // 65536 threads
    for (int i = gt; i < NRES * NH; i += 65536) {
        g_nh16[i] = __float2half_rn(node_h[i]);
        g_se16[i] = __float2half_rn(seq_emb[i]);
    }
    if (gt < 49152) {
        const int which = gt >> 14, r = gt & 16383;
        const int n = r >> 7, k = r & 127;
        const int kb = (which == 0) ? 0 : (which == 1 ? 128 : 384);
        g_mWh[gt] = __float2half_rn(mW1[(size_t)(kb + k) * NH + n]);
    }
    {
        const int n = gt >> 7, k = gt & 127;
        g_fW1h[gt] = __float2half_rn(fW1[(size_t)k * 512 + n]);
    }
    {
        const int n = gt >> 9, k = gt & 511;
        g_fW2h[gt] = __float2half_rn(fW2[(size_t)k * 128 + n]);
    }
}

// ---------------------------------------------------------------------------
// Kernel 1: Pi/Pj/Ps via fp16 HMMA (proven round-15 config)
// ---------------------------------------------------------------------------
#define LDB 272u
#define K1_A 0u
#define K1_W 17408u
#define K1_TOT 52224u

__global__ __launch_bounds__(256) void k1_hmma() {
    extern __shared__ char smc[];
    const uint32_t sb = smem_u32(smc);
    const int tid = threadIdx.x;
    const int w   = tid >> 5, lane = tid & 31;
    const int gid = lane >> 2, t4 = lane & 3;
    const int wm  = w >> 2, wn = w & 3;
    const int m_base = wm * 32, n_base = wn * 32;
    const int m0    = blockIdx.x * 64;
    const int which = blockIdx.y;

    const __half* Asrc = ((which == 2) ? g_se16 : g_nh16) + (size_t)m0 * NH;
    const __half* Wsrc = g_mWh + which * 16384;
    float* out = (which == 0) ? g_Pi : (which == 1 ? g_Pj : g_Ps);

    for (int i = tid; i < 1024; i += 256) {
        const int r = i >> 4, c = i & 15;
        asm volatile("cp.async.cg.shared.global [%0], [%1], 16;"
                     :: "r"(sb + K1_A + (uint32_t)r * LDB + (uint32_t)c * 16u),
                        "l"((const char*)Asrc + (size_t)r * 256 + (size_t)c * 16));
    }
    for (int i = tid; i < 2048; i += 256) {
        const int r = i >> 4, c = i & 15;
        asm volatile("cp.async.cg.shared.global [%0], [%1], 16;"
                     :: "r"(sb + K1_W + (uint32_t)r * LDB + (uint32_t)c * 16u),
                        "l"((const char*)Wsrc + (size_t)r * 256 + (size_t)c * 16));
    }
    asm volatile("cp.async.commit_group;" ::: "memory");
    asm volatile("cp.async.wait_group 0;" ::: "memory");
    __syncthreads();

    const uint32_t aBase = sb + K1_A + (uint32_t)(m_base + (lane & 15)) * LDB
                         + (uint32_t)((lane >> 4) * 16);
    const uint32_t b_off = (uint32_t)(lane & 7) * LDB + (uint32_t)(((lane >> 3) & 1) * 16);
    uint32_t bOf[4];
#pragma unroll
    for (int j = 0; j < 4; j++)
        bOf[j] = sb + K1_W + (uint32_t)(n_base + j * 8) * LDB + b_off;

    float acc[2][4][4];
#pragma unroll
    for (int i = 0; i < 2; i++)
#pragma unroll
        for (int j = 0; j < 4; j++)
#pragma unroll
            for (int q = 0; q < 4; q++) acc[i][j][q] = 0.f;

#pragma unroll
    for (int ks = 0; ks < 8; ks++) {
        const uint32_t ko = (uint32_t)ks * 32u;
        uint32_t a[2][4], bh[4][2];
        ldm_x4(a[0][0], a[0][1], a[0][2], a[0][3], aBase + ko);
        ldm_x4(a[1][0], a[1][1], a[1][2], a[1][3], aBase + 16u * LDB + ko);
#pragma unroll
        for (int j = 0; j < 4; j++)
            ldm_x2(bh[j][0], bh[j][1], bOf[j] + ko);
#pragma unroll
        for (int i = 0; i < 2; i++)
#pragma unroll
            for (int j = 0; j < 4; j++)
                mma_f16(acc[i][j], a[i][0], a[i][1], a[i][2], a[i][3], bh[j][0], bh[j][1]);
    }

#pragma unroll
    for (int i = 0; i < 2; i++) {
        const int rA = m_base + i * 16 + gid;
#pragma unroll
        for (int j = 0; j < 4; j++) {
            const int n_e = n_base + j * 8 + t4 * 2;
            *(float2*)&out[(size_t)(m0 + rA) * NH + n_e]     = make_float2(acc[i][j][0], acc[i][j][1]);
            *(float2*)&out[(size_t)(m0 + rA + 8) * NH + n_e] = make_float2(acc[i][j][2], acc[i][j][3]);
        }
    }
}

// ---------------------------------------------------------------------------
// Kernel 2: per-edge MLP, single-pass fp16 HMMA (round-15 proven config).
// CHANGE vs round-15: full 128-row cp.async staging (no direct-LDG rows).
// smem 173KB, 1 CTA/SM.
// ---------------------------------------------------------------------------
#define S_W1  0u
#define S_W2  34816u
#define S_A   69632u
#define S_STG 104448u    // 128 rows x 512 B fp32 staging (65536)
#define S_SSUM 169984u   // 8*128 fp32
#define S_IDX 174080u    // [2][128] int
#define S_AM  175104u    // [2][128] float
#define S_MB  176128u    // 256 fp32
#define S_K2TOT 177152u

__device__ __forceinline__ void do_prefetch(uint32_t sb, const float* edge_h,
                                            const int* edge_idx, const float* ar_mask,
                                            int row0, int pp, int tid) {
    const char* src = (const char*)(edge_h + (size_t)row0 * NH);
#pragma unroll
    for (int k = 0; k < 8; k++) {
        uint32_t off = (uint32_t)(tid + k * 512) * 16u;
        asm volatile("cp.async.cg.shared.global [%0], [%1], 16;"
                     :: "r"(sb + S_STG + off), "l"(src + off));
    }
    if (tid < 128)
        asm volatile("cp.async.ca.shared.global [%0], [%1], 4;"
                     :: "r"(sb + S_IDX + (uint32_t)pp * 512u + (uint32_t)tid * 4u),
                        "l"(edge_idx + row0 + tid));
    else if (tid < 256)
        asm volatile("cp.async.ca.shared.global [%0], [%1], 4;"
                     :: "r"(sb + S_AM + (uint32_t)pp * 512u + (uint32_t)(tid - 128) * 4u),
                        "l"(ar_mask + row0 + (tid - 128)));
    asm volatile("cp.async.commit_group;" ::: "memory");
}

__global__ __launch_bounds__(512) void k2_msg(const float* __restrict__ edge_h,
                                              const int*   __restrict__ edge_idx,
                                              const float* __restrict__ ar_mask,
                                              const float* __restrict__ mW1,
                                              const float* __restrict__ mb1,
                                              const float* __restrict__ mW2,
                                              const float* __restrict__ mb2,
                                              int ngroups) {
    extern __shared__ char sm[];
    const int tid  = threadIdx.x;
    const int w    = tid >> 5, lane = tid & 31;
    const int gid  = lane >> 2, t4 = lane & 3;
    const int wm   = w >> 2, wn = w & 3;
    const int m_base = wm * 32, n_base = wn * 32;
    const uint32_t sb = smem_u32(sm);

    float* SSUM = (float*)(sm + S_SSUM);
    float* MB   = (float*)(sm + S_MB);
    float* STG  = (float*)(sm + S_STG);

    if (tid < 128) MB[tid] = mb1[tid];
    else if (tid < 256) MB[tid] = mb2[tid - 128];

    for (int idx = tid; idx < 16384; idx += 512) {
        const int n = idx & 127, k = idx >> 7;
        float w1 = mW1[(size_t)(256 + k) * NH + n];
        float w2 = mW2[(size_t)k * NH + n];
        const uint32_t o = (uint32_t)n * LDB + (uint32_t)k * 2u;
        *(__half*)(sm + S_W1 + o) = __float2half_rn(w1);
        *(__half*)(sm + S_W2 + o) = __float2half_rn(w2);
    }

    const uint32_t aBase = sb + S_A + (uint32_t)(m_base + (lane & 15)) * LDB
                         + (uint32_t)((lane >> 4) * 16);
    const uint32_t b_off = (uint32_t)(lane & 7) * LDB + (uint32_t)(((lane >> 3) & 1) * 16);
    uint32_t bOf[4];
#pragma unroll
    for (int j = 0; j < 4; j++)
        bOf[j] = (uint32_t)(n_base + j * 8) * LDB + b_off;

    int pp = 0;
    if ((int)blockIdx.x < ngroups)
        do_prefetch(sb, edge_h, edge_idx, ar_mask, blockIdx.x * 384, 0, tid);

    for (int g = blockIdx.x; g < ngroups; g += gridDim.x) {
        for (int t = 0; t < 3; t++) {
            const int row0 = g * 384 + t * 128;
            asm volatile("cp.async.wait_group 0;" ::: "memory");
            __syncthreads();
            if (t == 0)
                for (int i = tid; i < 1024; i += 512) SSUM[i] = 0.f;

            // staged rows 0-127 -> A fp16
#pragma unroll
            for (int k2i = 0; k2i < 8; k2i++) {
                const int i = tid + k2i * 512;
                const int r = i >> 5, c4 = i & 31;
                float4 e = *(const float4*)((const char*)STG + (size_t)i * 16);
                const uint32_t o = (uint32_t)r * LDB + (uint32_t)c4 * 8u;
                *(uint2*)(sm + S_A + o) = make_uint2(pack_h2(e.x, e.y), pack_h2(e.z, e.w));
            }
            __syncthreads();

            // prefetch next tile
            {
                int nt = t + 1, ng = g;
                if (nt == 3) { nt = 0; ng = g + gridDim.x; }
                if (ng < ngroups)
                    do_prefetch(sb, edge_h, edge_idx, ar_mask, ng * 384 + nt * 128, pp ^ 1, tid);
            }

            const int*   IDXc = (const int*)(sm + S_IDX) + pp * 128;
            const float* AMc  = (const float*)(sm + S_AM) + pp * 128;

            float acc[2][4][4];

#pragma unroll
            for (int i = 0; i < 2; i++) {
                const int rA = m_base + i * 16 + gid;
                const int resA = (row0 + rA) / NK,  resB = (row0 + rA + 8) / NK;
                const int nbrA = IDXc[rA],          nbrB = IDXc[rA + 8];
                const float amA = AMc[rA],          amB = AMc[rA + 8];
                const float* PiA = g_Pi + (size_t)resA * NH;
                const float* PiB = g_Pi + (size_t)resB * NH;
                const float* PjA = g_Pj + (size_t)nbrA * NH;
                const float* PjB = g_Pj + (size_t)nbrB * NH;
                const float* PsA = g_Ps + (size_t)nbrA * NH;
                const float* PsB = g_Ps + (size_t)nbrB * NH;
#pragma unroll
                for (int j = 0; j < 4; j++) {
                    const int n_e = n_base + j * 8 + t4 * 2;
                    float2 piA = *(const float2*)&PiA[n_e], piB = *(const float2*)&PiB[n_e];
                    float2 pjA = *(const float2*)&PjA[n_e], pjB = *(const float2*)&PjB[n_e];
                    float2 psA = *(const float2*)&PsA[n_e], psB = *(const float2*)&PsB[n_e];
                    float2 mb = *(const float2*)&MB[n_e];
                    acc[i][j][0] = piA.x + pjA.x + amA * psA.x + mb.x;
                    acc[i][j][1] = piA.y + pjA.y + amA * psA.y + mb.y;
                    acc[i][j][2] = piB.x + pjB.x + amB * psB.x + mb.x;
                    acc[i][j][3] = piB.y + pjB.y + amB * psB.y + mb.y;
                }
            }
#pragma unroll
            for (int ks = 0; ks < 8; ks++) {
                const uint32_t ko = (uint32_t)ks * 32u;
                uint32_t a[2][4], bh[4][2];
                ldm_x4(a[0][0], a[0][1], a[0][2], a[0][3], aBase + ko);
                ldm_x4(a[1][0], a[1][1], a[1][2], a[1][3], aBase + 16u * LDB + ko);
#pragma unroll
                for (int j = 0; j < 4; j++)
                    ldm_x2(bh[j][0], bh[j][1], sb + S_W1 + bOf[j] + ko);
#pragma unroll
                for (int i = 0; i < 2; i++)
#pragma unroll
                    for (int j = 0; j < 4; j++)
                        mma_f16(acc[i][j], a[i][0], a[i][1], a[i][2], a[i][3], bh[j][0], bh[j][1]);
            }
            __syncthreads();

#pragma unroll
            for (int i = 0; i < 2; i++) {
                const int m_e = m_base + i * 16 + gid;
#pragma unroll
                for (int j = 0; j < 4; j++) {
                    const int n_e = n_base + j * 8 + t4 * 2;
                    float v0 = gelu_fast(acc[i][j][0]), v1 = gelu_fast(acc[i][j][1]);
                    float v2 = gelu_fast(acc[i][j][2]), v3 = gelu_fast(acc[i][j][3]);
                    const uint32_t o0 = (uint32_t)m_e * LDB + (uint32_t)n_e * 2u;
                    const uint32_t o1 = o0 + 8u * LDB;
                    *(uint32_t*)(sm + S_A + o0) = pack_h2(v0, v1);
                    *(uint32_t*)(sm + S_A + o1) = pack_h2(v2, v3);
                }
            }
            __syncthreads();

#pragma unroll
            for (int i = 0; i < 2; i++)
#pragma unroll
                for (int j = 0; j < 4; j++) {
                    float2 mb = *(const float2*)&MB[128 + n_base + j * 8 + t4 * 2];
                    acc[i][j][0] = mb.x; acc[i][j][1] = mb.y;
                    acc[i][j][2] = mb.x; acc[i][j][3] = mb.y;
                }
#pragma unroll
            for (int ks = 0; ks < 8; ks++) {
                const uint32_t ko = (uint32_t)ks * 32u;
                uint32_t a[2][4], bh[4][2];
                ldm_x4(a[0][0], a[0][1], a[0][2], a[0][3], aBase + ko);
                ldm_x4(a[1][0], a[1][1], a[1][2], a[1][3], aBase + 16u * LDB + ko);
#pragma unroll
                for (int j = 0; j < 4; j++)
                    ldm_x2(bh[j][0], bh[j][1], sb + S_W2 + bOf[j] + ko);
#pragma unroll
                for (int i = 0; i < 2; i++)
#pragma unroll
                    for (int j = 0; j < 4; j++)
                        mma_f16(acc[i][j], a[i][0], a[i][1], a[i][2], a[i][3], bh[j][0], bh[j][1]);
            }

            {
                const int R0  = t * 128 + m_base;
                const int rl0 = R0 / NK;
                const int bb  = (rl0 + 1) * NK - R0;
#pragma unroll
                for (int j = 0; j < 4; j++) {
#pragma unroll
                    for (int p = 0; p < 2; p++) {
                        float y0 = gelu_fast(acc[0][j][p]);
                        float y1 = gelu_fast(acc[0][j][p + 2]);
                        float y2 = gelu_fast(acc[1][j][p]);
                        float y3 = gelu_fast(acc[1][j][p + 2]);
                        float s0 = 0.f, s1 = 0.f;
                        if (gid      < bb) s0 += y0; else s1 += y0;
                        if (gid + 8  < bb) s0 += y1; else s1 += y1;
                        if (gid + 16 < bb) s0 += y2; else s1 += y2;
                        if (gid + 24 < bb) s0 += y3; else s1 += y3;
#pragma unroll
                        for (int o = 4; o <= 16; o <<= 1) {
                            s0 += __shfl_xor_sync(0xffffffffu, s0, o);
                            s1 += __shfl_xor_sync(0xffffffffu, s1, o);
                        }
                        if (gid == 0) {
                            const int c = n_base + j * 8 + t4 * 2 + p;
                            atomicAdd(&SSUM[rl0 * 128 + c], s0);
                            if (bb < 32) atomicAdd(&SSUM[(rl0 + 1) * 128 + c], s1);
                        }
                    }
                }
            }
            pp ^= 1;
        }
        __syncthreads();
        for (int i = tid; i < 1024; i += 512)
            g_S[(size_t)g * 1024 + i] = SSUM[i];
    }
}

// ---------------------------------------------------------------------------
// Kernel 3: GEMM3+LN1 fp32 (mW3 2x32KB chunks); FFN fp16 HMMA, streamed
// pre-converted weights; 93.7KB smem, 2 CTAs/SM (proven round-14/15)
// ---------------------------------------------------------------------------
#define K3_H1  0u
#define K3_A16 16896u
#define K3_T16 25600u
#define K3_WB  58880u
#define K3_TOT 93696u
#define LDT 1040u

__device__ __forceinline__ void k3_wload(uint32_t dst, const __half* src,
                                         uint32_t row_stride_b, int tid) {
#pragma unroll
    for (int i = 0; i < 8; i++) {
        const int c = tid + i * 256;
        const int r = c >> 4, col = c & 15;
        asm volatile("cp.async.cg.shared.global [%0], [%1], 16;"
                     :: "r"(dst + (uint32_t)r * LDB + (uint32_t)col * 16u),
                        "l"((const char*)src + (size_t)r * row_stride_b + (size_t)col * 16));
    }
    asm volatile("cp.async.commit_group;" ::: "memory");
}

__global__ __launch_bounds__(256, 2) void k3_ff(const float* __restrict__ node_h,
                                                const float* __restrict__ mW3,
                                                const float* __restrict__ mb3,
                                                const float* __restrict__ fb1,
                                                const float* __restrict__ fb2,
                                                const float* __restrict__ g1,
                                                const float* __restrict__ b1,
                                                const float* __restrict__ g2,
                                                const float* __restrict__ b2,
                                                float* __restrict__ out) {
    extern __shared__ char smc[];
    float* H1sh = (float*)(smc + K3_H1);
    float* Ssh  = (float*)(smc + K3_T16);
    float* WfA  = (float*)(smc + K3_WB);
    const uint32_t sb = smem_u32(smc);

    const int tid = threadIdx.x;
    const int w   = tid >> 5, lane = tid & 31;
    const int gid = lane >> 2, t4 = lane & 3;
    const int wm  = w >> 2, wn = w & 3;
    const int m0  = blockIdx.x * 32;
    const int tc  = tid & 15, tr = tid >> 4;

    for (int i = tid; i < 1024; i += 256) {
        int r = i >> 5, c4 = i & 31;
        *(float4*)&Ssh[r * 132 + c4 * 4] = ((const float4*)(g_S + (size_t)(m0 + r) * NH))[c4];
    }
    {
        float acc[2][8];
#pragma unroll
        for (int i = 0; i < 2; i++)
#pragma unroll
            for (int j = 0; j < 8; j++)
                acc[i][j] = 48.f * mb3[(j < 4 ? tc * 4 + j : 64 + tc * 4 + j - 4)];
        for (int h = 0; h < 2; h++) {
            __syncthreads();
            for (int i = tid; i < 2048; i += 256) {
                int k = i >> 5, c4 = i & 31;
                ((float4*)&WfA[k * 128])[c4] = ((const float4*)&mW3[(size_t)(h * 64 + k) * 128])[c4];
            }
            __syncthreads();
#pragma unroll 4
            for (int kk = 0; kk < 64; kk++) {
                float4 b0 = *(const float4*)&WfA[kk * 128 + tc * 4];
                float4 b1v = *(const float4*)&WfA[kk * 128 + 64 + tc * 4];
#pragma unroll
                for (int i = 0; i < 2; i++) {
                    float a = Ssh[(tr * 2 + i) * 132 + h * 64 + kk];
                    acc[i][0] = fmaf(a, b0.x, acc[i][0]); acc[i][1] = fmaf(a, b0.y, acc[i][1]);
                    acc[i][2] = fmaf(a, b0.z, acc[i][2]); acc[i][3] = fmaf(a, b0.w, acc[i][3]);
                    acc[i][4] = fmaf(a, b1v.x, acc[i][4]); acc[i][5] = fmaf(a, b1v.y, acc[i][5]);
                    acc[i][6] = fmaf(a, b1v.z, acc[i][6]); acc[i][7] = fmaf(a, b1v.w, acc[i][7]);
                }
            }
        }
#pragma unroll
        for (int i = 0; i < 2; i++) {
            const float* nrow = node_h + (size_t)(m0 + tr * 2 + i) * NH;
            float4 n0 = *(const float4*)&nrow[tc * 4];
            float4 n1 = *(const float4*)&nrow[64 + tc * 4];
            float* hrow = &H1sh[(tr * 2 + i) * 132];
            hrow[tc * 4 + 0] = acc[i][0] + n0.x; hrow[tc * 4 + 1] = acc[i][1] + n0.y;
            hrow[tc * 4 + 2] = acc[i][2] + n0.z; hrow[tc * 4 + 3] = acc[i][3] + n0.w;
            hrow[64 + tc * 4 + 0] = acc[i][4] + n1.x; hrow[64 + tc * 4 + 1] = acc[i][5] + n1.y;
            hrow[64 + tc * 4 + 2] = acc[i][6] + n1.z; hrow[64 + tc * 4 + 3] = acc[i][7] + n1.w;
        }
    }
    __syncthreads();

    k3_wload(sb + K3_WB, g_fW1h, 256u, tid);

    for (int r = w; r < 32; r += 8) {
        const int c0 = lane * 4;
        float v0 = H1sh[r * 132 + c0], v1 = H1sh[r * 132 + c0 + 1];
        float v2 = H1sh[r * 132 + c0 + 2], v3 = H1sh[r * 132 + c0 + 3];
        float s = v0 + v1 + v2 + v3;
#pragma unroll
        for (int o = 16; o; o >>= 1) s += __shfl_xor_sync(0xffffffffu, s, o);
        float mu = s * (1.f / 128.f);
        float d0 = v0 - mu, d1 = v1 - mu, d2 = v2 - mu, d3 = v3 - mu;
        float q = d0 * d0 + d1 * d1 + d2 * d2 + d3 * d3;
#pragma unroll
        for (int o = 16; o; o >>= 1) q += __shfl_xor_sync(0xffffffffu, q, o);
        float rs = rsqrtf(q * (1.f / 128.f) + 1e-5f);
        H1sh[r * 132 + c0]     = d0 * rs * g1[c0]     + b1[c0];
        H1sh[r * 132 + c0 + 1] = d1 * rs * g1[c0 + 1] + b1[c0 + 1];
        H1sh[r * 132 + c0 + 2] = d2 * rs * g1[c0 + 2] + b1[c0 + 2];
        H1sh[r * 132 + c0 + 3] = d3 * rs * g1[c0 + 3] + b1[c0 + 3];
    }
    __syncthreads();

    {
        const int r = tid >> 3, c0 = (tid & 7) * 16;
        const float* hrow = &H1sh[r * 132 + c0];
        uint32_t pk[8];
#pragma unroll
        for (int j = 0; j < 8; j++) pk[j] = pack_h2(hrow[j * 2], hrow[j * 2 + 1]);
        char* dst = smc + K3_A16 + (uint32_t)r * LDB + (uint32_t)c0 * 2u;
        *(uint4*)dst        = make_uint4(pk[0], pk[1], pk[2], pk[3]);
        *(uint4*)(dst + 16) = make_uint4(pk[4], pk[5], pk[6], pk[7]);
    }

    const uint32_t aAddr1 = sb + K3_A16 + (uint32_t)(wm * 16 + (lane & 15)) * LDB
                          + (uint32_t)((lane >> 4) * 16);
    const uint32_t aAddr2 = sb + K3_T16 + (uint32_t)(wm * 16 + (lane & 15)) * LDT
                          + (uint32_t)((lane >> 4) * 16);
    const uint32_t b_off = (uint32_t)(lane & 7) * LDB + (uint32_t)(((lane >> 3) & 1) * 16);
    uint32_t bOf[4];
#pragma unroll
    for (int j = 0; j < 4; j++)
        bOf[j] = (uint32_t)(wn * 32 + j * 8) * LDB + b_off;
    const uint32_t WBa = sb + K3_WB;

    float acc2[4][4];
#pragma unroll
    for (int j = 0; j < 4; j++) {
        float2 fb = *(const float2*)&fb2[wn * 32 + j * 8 + t4 * 2];
        acc2[j][0] = fb.x; acc2[j][1] = fb.y; acc2[j][2] = fb.x; acc2[j][3] = fb.y;
    }

    for (int nc = 0; nc < 4; nc++) {
        asm volatile("cp.async.wait_group 0;" ::: "memory");
        __syncthreads();
        float acc[4][4];
#pragma unroll
        for (int j = 0; j < 4; j++) {
            float2 fb = *(const float2*)&fb1[nc * 128 + wn * 32 + j * 8 + t4 * 2];
            acc[j][0] = fb.x; acc[j][1] = fb.y; acc[j][2] = fb.x; acc[j][3] = fb.y;
        }
#pragma unroll
        for (int ks = 0; ks < 8; ks++) {
            const uint32_t ko = (uint32_t)ks * 32u;
            uint32_t a[4], bh[4][2];
            ldm_x4(a[0], a[1], a[2], a[3], aAddr1 + ko);
#pragma unroll
            for (int j = 0; j < 4; j++)
                ldm_x2(bh[j][0], bh[j][1], WBa + bOf[j] + ko);
#pragma unroll
            for (int j = 0; j < 4; j++)
                mma_f16(acc[j], a[0], a[1], a[2], a[3], bh[j][0], bh[j][1]);
        }
        __syncthreads();
        if (nc < 3)      k3_wload(WBa, g_fW1h + (nc + 1) * 16384, 256u, tid);
        else             k3_wload(WBa, g_fW2h,                    1024u, tid);
#pragma unroll
        for (int j = 0; j < 4; j++) {
            const int r0 = wm * 16 + gid;
            const int cg = nc * 128 + wn * 32 + j * 8 + t4 * 2;
            *(uint32_t*)(smc + K3_T16 + (uint32_t)r0 * LDT + (uint32_t)cg * 2u) =
                pack_h2(gelu_fast(acc[j][0]), gelu_fast(acc[j][1]));
            *(uint32_t*)(smc + K3_T16 + (uint32_t)(r0 + 8) * LDT + (uint32_t)cg * 2u) =
                pack_h2(gelu_fast(acc[j][2]), gelu_fast(acc[j][3]));
        }
    }

    for (int kc = 0; kc < 4; kc++) {
        asm volatile("cp.async.wait_group 0;" ::: "memory");
        __syncthreads();
#pragma unroll
        for (int ks = 0; ks < 8; ks++) {
            const uint32_t ko = (uint32_t)ks * 32u;
            uint32_t a[4], bh[4][2];
            ldm_x4(a[0], a[1], a[2], a[3], aAddr2 + (uint32_t)kc * 256u + ko);
#pragma unroll
            for (int j = 0; j < 4; j++)
                ldm_x2(bh[j][0], bh[j][1], WBa + bOf[j] + ko);
#pragma unroll
            for (int j = 0; j < 4; j++)
                mma_f16(acc2[j], a[0], a[1], a[2], a[3], bh[j][0], bh[j][1]);
        }
        __syncthreads();
        if (kc < 3) k3_wload(WBa, g_fW2h + (kc + 1) * 128, 1024u, tid);
    }

    __syncthreads();
    float* Vsh = (float*)(smc + K3_T16);
#pragma unroll
    for (int j = 0; j < 4; j++) {
        const int r0 = wm * 16 + gid, r1 = r0 + 8;
        const int c = wn * 32 + j * 8 + t4 * 2;
        Vsh[r0 * 132 + c]     = H1sh[r0 * 132 + c]     + acc2[j][0];
        Vsh[r0 * 132 + c + 1] = H1sh[r0 * 132 + c + 1] + acc2[j][1];
        Vsh[r1 * 132 + c]     = H1sh[r1 * 132 + c]     + acc2[j][2];
        Vsh[r1 * 132 + c + 1] = H1sh[r1 * 132 + c + 1] + acc2[j][3];
    }
    __syncthreads();
    for (int r = w; r < 32; r += 8) {
        const int c0 = lane * 4;
        float v0 = Vsh[r * 132 + c0], v1 = Vsh[r * 132 + c0 + 1];
        float v2 = Vsh[r * 132 + c0 + 2], v3 = Vsh[r * 132 + c0 + 3];
        float s = v0 + v1 + v2 + v3;
#pragma unroll
        for (int o = 16; o; o >>= 1) s += __shfl_xor_sync(0xffffffffu, s, o);
        float mu = s * (1.f / 128.f);
        float d0 = v0 - mu, d1 = v1 - mu, d2 = v2 - mu, d3 = v3 - mu;
        float q = d0 * d0 + d1 * d1 + d2 * d2 + d3 * d3;
#pragma unroll
        for (int o = 16; o; o >>= 1) q += __shfl_xor_sync(0xffffffffu, q, o);
        float rs = rsqrtf(q * (1.f / 128.f) + 1e-5f);
        float4 o4;
        o4.x = d0 * rs * g2[c0]     + b2[c0];
        o4.y = d1 * rs * g2[c0 + 1] + b2[c0 + 1];
        o4.z = d2 * rs * g2[c0 + 2] + b2[c0 + 2];
        o4.w = d3 * rs * g2[c0 + 3] + b2[c0 + 3];
        *(float4*)&out[(size_t)(m0 + r) * NH + c0] = o4;
    }
}

// ---------------------------------------------------------------------------
extern "C" void kernel_launch(void* const* d_in, const int* in_sizes, int n_in,
                              void* d_out, int out_size) {
    const float* node_h   = (const float*)d_in[0];
    const float* edge_h   = (const float*)d_in[1];
    const int*   edge_idx = (const int*)d_in[2];
    const float* seq_emb  = (const float*)d_in[3];
    const float* ar_mask  = (const float*)d_in[4];
    const float* mW1 = (const float*)d_in[5];
    const float* mb1 = (const float*)d_in[6];
    const float* mW2 = (const float*)d_in[7];
    const float* mb2 = (const float*)d_in[8];
    const float* mW3 = (const float*)d_in[9];
    const float* mb3 = (const float*)d_in[10];
    const float* fW1 = (const float*)d_in[11];
    const float* fb1 = (const float*)d_in[12];
    const float* fW2 = (const float*)d_in[13];
    const float* fb2 = (const float*)d_in[14];
    const float* g1  = (const float*)d_in[15];
    const float* b1  = (const float*)d_in[16];
    const float* g2  = (const float*)d_in[17];
    const float* b2  = (const float*)d_in[18];
    float* out = (float*)d_out;

    int dev = 0;
    cudaGetDevice(&dev);
    int nsm = 148;
    cudaDeviceGetAttribute(&nsm, cudaDevAttrMultiProcessorCount, dev);

    cudaFuncSetAttribute(k1_hmma, cudaFuncAttributeMaxDynamicSharedMemorySize, (int)K1_TOT);
    cudaFuncSetAttribute(k2_msg,  cudaFuncAttributeMaxDynamicSharedMemorySize, (int)S_K2TOT);
    cudaFuncSetAttribute(k3_ff,   cudaFuncAttributeMaxDynamicSharedMemorySize, (int)K3_TOT);

    k0_conv<<<256, 256>>>(node_h, seq_emb, mW1, fW1, fW2);

    dim3 grid1(NRES / 64, 3);
    k1_hmma<<<grid1, 256, K1_TOT>>>();

    const int ngroups = NRES / 8;
    k2_msg<<<nsm, 512, S_K2TOT>>>(edge_h, edge_idx, ar_mask,
                                  mW1, mb1, mW2, mb2, ngroups);

    k3_ff<<<NRES / 32, 256, K3_TOT>>>(node_h, mW3, mb3, fb1, fb2,
                                      g1, b1, g2, b2, out);
}